// round 10
// baseline (speedup 1.0000x reference)
#include <cuda_runtime.h>
#include <math.h>

#define SEQT 2048
#define INSZ 512
#define HID  1024
#define G4   4096   // 4*HID
#define OUTD 4

// ---------------- scratch (static device allocations only) ----------------
__device__ float g_gx[SEQT * G4];     // 32 MB: input projections + biases
__device__ float g_ys[SEQT * HID];    // 8 MB: LSTM outputs
__device__ float g_h1[SEQT * HID];    // 8 MB
__device__ float g_h2[SEQT * HID];    // 8 MB
__device__ float g_hbuf[2][HID];      // double-buffered recurrent state
__device__ unsigned g_arrive;         // monotonic arrival counter (reset each launch)

// ---------------- tiled SGEMM: C[M,N] = A[M,K] @ B[N,K]^T + bias (+bias2), opt ReLU
__global__ void __launch_bounds__(256) sgemm_bt(
    const float* __restrict__ A, const float* __restrict__ B,
    const float* __restrict__ bias, const float* __restrict__ bias2,
    float* __restrict__ C, int M, int N, int K, int relu)
{
    __shared__ float As[16][64];
    __shared__ float Bs[16][64];
    int tid = threadIdx.x;
    int tx = tid & 15, ty = tid >> 4;
    int m0 = blockIdx.y * 64, n0 = blockIdx.x * 64;

    int lm  = tid >> 2;
    int lk4 = tid & 3;

    const float4* Ag = (const float4*)(A + (size_t)(m0 + lm) * K) + lk4;
    const float4* Bg = (const float4*)(B + (size_t)(n0 + lm) * K) + lk4;

    float acc[4][4] = {};

    for (int k0 = 0; k0 < K; k0 += 16) {
        float4 av = *Ag; Ag += 4;
        float4 bv = *Bg; Bg += 4;
        __syncthreads();
        As[lk4 * 4 + 0][lm] = av.x; As[lk4 * 4 + 1][lm] = av.y;
        As[lk4 * 4 + 2][lm] = av.z; As[lk4 * 4 + 3][lm] = av.w;
        Bs[lk4 * 4 + 0][lm] = bv.x; Bs[lk4 * 4 + 1][lm] = bv.y;
        Bs[lk4 * 4 + 2][lm] = bv.z; Bs[lk4 * 4 + 3][lm] = bv.w;
        __syncthreads();
        #pragma unroll
        for (int k = 0; k < 16; k++) {
            float4 a4 = *(const float4*)&As[k][ty * 4];
            float4 b4 = *(const float4*)&Bs[k][tx * 4];
            float a_[4] = {a4.x, a4.y, a4.z, a4.w};
            float b_[4] = {b4.x, b4.y, b4.z, b4.w};
            #pragma unroll
            for (int i = 0; i < 4; i++)
                #pragma unroll
                for (int j = 0; j < 4; j++)
                    acc[i][j] = fmaf(a_[i], b_[j], acc[i][j]);
        }
    }

    int n = n0 + tx * 4;
    float bb[4];
    #pragma unroll
    for (int j = 0; j < 4; j++) {
        bb[j] = bias ? bias[n + j] : 0.f;
        if (bias2) bb[j] += bias2[n + j];
    }
    #pragma unroll
    for (int i = 0; i < 4; i++) {
        int m = m0 + ty * 4 + i;
        float4 r;
        r.x = acc[i][0] + bb[0];
        r.y = acc[i][1] + bb[1];
        r.z = acc[i][2] + bb[2];
        r.w = acc[i][3] + bb[3];
        if (relu) {
            r.x = fmaxf(r.x, 0.f); r.y = fmaxf(r.y, 0.f);
            r.z = fmaxf(r.z, 0.f); r.w = fmaxf(r.w, 0.f);
        }
        *(float4*)&C[(size_t)m * N + n] = r;
    }
}

// ---------------- sync helpers ----------------
__device__ __forceinline__ unsigned ld_acq_gpu(const unsigned* p)
{
    unsigned v;
    asm volatile("ld.acquire.gpu.global.u32 %0, [%1];" : "=r"(v) : "l"(p) : "memory");
    return v;
}

__device__ __forceinline__ void red_release_add(unsigned* p, unsigned v)
{
    asm volatile("red.release.gpu.global.add.u32 [%0], %1;" :: "l"(p), "r"(v) : "memory");
}

__device__ __forceinline__ float tanh_approx(float x)
{
    float r;
    asm("tanh.approx.f32 %0, %1;" : "=f"(r) : "f"(x));
    return r;
}

__device__ __forceinline__ float sigmoidf_(float x) { return 1.f / (1.f + __expf(-x)); }

__global__ void reset_kernel() { g_arrive = 0u; }

// ---------------- persistent LSTM recurrence ----------------
// grid = 128 blocks x 256 threads (8 warps). Warp w of block b owns hidden unit
// hu = 8b + w, computing all 4 gate rows {g*HID + hu}. Lane l covers k-slice
// {l + 32*i : i=0..7} (float4 granularity) of the dot products, so h is loaded
// ONCE per lane (8 float4 = 128B, straight from L2) and reused for all 4 rows.
// Arrival protocol: after producing its h(t) slice, each block does a
// red.release add; reading h(t) requires g_arrive >= 128*(t+1).
#define LSTM_BLOCKS 128
__global__ void __launch_bounds__(256, 1) lstm_kernel(
    const float* __restrict__ gx, const float* __restrict__ w_hh,
    const float* __restrict__ h0, const float* __restrict__ c0,
    float* __restrict__ ys, float* __restrict__ out)
{
    int tid  = threadIdx.x;
    int warp = tid >> 5, lane = tid & 31;
    int hu   = blockIdx.x * 8 + warp;          // 0..1023

    const float4* w0 = (const float4*)(w_hh + (size_t)(0 * HID + hu) * HID) + lane;
    const float4* w1 = (const float4*)(w_hh + (size_t)(1 * HID + hu) * HID) + lane;
    const float4* w2 = (const float4*)(w_hh + (size_t)(2 * HID + hu) * HID) + lane;
    const float4* w3 = (const float4*)(w_hh + (size_t)(3 * HID + hu) * HID) + lane;
    const float*  gxp = gx + (size_t)(lane & 3) * HID + hu;   // lanes 0..3 prefetch gates

    float c = c0[hu];
    float hlast = h0[hu];
    if (lane == 0) __stcg(&g_hbuf[0][hu], hlast);
    __syncthreads();
    if (tid == 0) red_release_add(&g_arrive, 1u);

    for (int t = 0; t < SEQT; t++) {
        const float4* hb  = (const float4*)g_hbuf[t & 1];
        float*        hbn = g_hbuf[(t & 1) ^ 1];

        // prefetch this step's gx gate values (independent of other blocks)
        float gxv = 0.f;
        if (lane < 4) gxv = __ldcs(gxp + (size_t)t * G4);

        // warp-local wait until all 128 blocks produced h(t)
        unsigned target = (unsigned)(LSTM_BLOCKS * (t + 1));
        if (lane == 0) {
            while (ld_acq_gpu(&g_arrive) < target) { }
        }
        __syncwarp();

        // load h slice once (8 coalesced LDG.128 from L2), reuse over 4 rows
        float4 hv[8];
        #pragma unroll
        for (int i = 0; i < 8; i++) hv[i] = __ldcg(hb + lane + (i << 5));

        float a0 = 0.f, a1 = 0.f, a2 = 0.f, a3 = 0.f;
        #pragma unroll
        for (int i = 0; i < 8; i++) {
            float4 u0 = __ldg(w0 + (i << 5));
            float4 u1 = __ldg(w1 + (i << 5));
            float4 u2 = __ldg(w2 + (i << 5));
            float4 u3 = __ldg(w3 + (i << 5));
            float4 x = hv[i];
            a0 = fmaf(u0.x, x.x, a0); a0 = fmaf(u0.y, x.y, a0);
            a0 = fmaf(u0.z, x.z, a0); a0 = fmaf(u0.w, x.w, a0);
            a1 = fmaf(u1.x, x.x, a1); a1 = fmaf(u1.y, x.y, a1);
            a1 = fmaf(u1.z, x.z, a1); a1 = fmaf(u1.w, x.w, a1);
            a2 = fmaf(u2.x, x.x, a2); a2 = fmaf(u2.y, x.y, a2);
            a2 = fmaf(u2.z, x.z, a2); a2 = fmaf(u2.w, x.w, a2);
            a3 = fmaf(u3.x, x.x, a3); a3 = fmaf(u3.y, x.y, a3);
            a3 = fmaf(u3.z, x.z, a3); a3 = fmaf(u3.w, x.w, a3);
        }

        // 4 interleaved warp reductions -> lane 0 holds all 4 gate pre-activations
        #pragma unroll
        for (int off = 16; off; off >>= 1) {
            a0 += __shfl_down_sync(0xffffffffu, a0, off);
            a1 += __shfl_down_sync(0xffffffffu, a1, off);
            a2 += __shfl_down_sync(0xffffffffu, a2, off);
            a3 += __shfl_down_sync(0xffffffffu, a3, off);
        }
        float gx_i = __shfl_sync(0xffffffffu, gxv, 0);
        float gx_f = __shfl_sync(0xffffffffu, gxv, 1);
        float gx_g = __shfl_sync(0xffffffffu, gxv, 2);
        float gx_o = __shfl_sync(0xffffffffu, gxv, 3);

        if (lane == 0) {
            float i_ = sigmoidf_(a0 + gx_i);
            float f_ = sigmoidf_(a1 + gx_f);
            float g_ = tanh_approx(a2 + gx_g);
            float o_ = sigmoidf_(a3 + gx_o);
            c = fmaf(f_, c, i_ * g_);
            float h = o_ * tanh_approx(c);
            hlast = h;
            __stcg(&hbn[hu], h);
            __stcs(&ys[(size_t)t * HID + hu], h);
        }
        __syncthreads();
        if (tid == 0) red_release_add(&g_arrive, 1u);
    }

    // hT at out[16384..17407], cT at out[17408..18431]
    if (lane == 0) {
        out[2 * SEQT * OUTD + hu] = hlast;
        out[2 * SEQT * OUTD + HID + hu] = c;
    }
}

// ---------------- policy head ----------------
__global__ void __launch_bounds__(128) head_kernel(
    const float* __restrict__ h2, const float* __restrict__ mean_w,
    const float* __restrict__ mean_b, const float* __restrict__ log_std,
    float* __restrict__ out)
{
    __shared__ float sh[HID];
    int t = blockIdx.x;
    for (int i = threadIdx.x; i < HID; i += 128) sh[i] = h2[(size_t)t * HID + i];
    __syncthreads();
    int w = threadIdx.x >> 5, lane = threadIdx.x & 31;
    const float* wr = mean_w + (size_t)w * HID;
    float acc = 0.f;
    for (int k = lane; k < HID; k += 32) acc = fmaf(wr[k], sh[k], acc);
    #pragma unroll
    for (int o = 16; o; o >>= 1) acc += __shfl_down_sync(0xffffffffu, acc, o);
    if (lane == 0) {
        out[(size_t)t * OUTD + w] = acc + mean_b[w];
        out[SEQT * OUTD + (size_t)t * OUTD + w] = log_std[w];
    }
}

// ---------------- launcher ----------------
extern "C" void kernel_launch(void* const* d_in, const int* in_sizes, int n_in,
                              void* d_out, int out_size)
{
    const float* x      = (const float*)d_in[0];
    const float* h0     = (const float*)d_in[1];
    const float* c0     = (const float*)d_in[2];
    const float* w_ih   = (const float*)d_in[3];
    const float* w_hh   = (const float*)d_in[4];
    const float* b_ih   = (const float*)d_in[5];
    const float* b_hh   = (const float*)d_in[6];
    const float* fc1_w  = (const float*)d_in[7];
    const float* fc1_b  = (const float*)d_in[8];
    const float* fc2_w  = (const float*)d_in[9];
    const float* fc2_b  = (const float*)d_in[10];
    const float* mean_w = (const float*)d_in[11];
    const float* mean_b = (const float*)d_in[12];
    const float* lstd   = (const float*)d_in[13];
    float* out = (float*)d_out;

    float *gx, *ys, *h1, *h2;
    cudaGetSymbolAddress((void**)&gx, g_gx);
    cudaGetSymbolAddress((void**)&ys, g_ys);
    cudaGetSymbolAddress((void**)&h1, g_h1);
    cudaGetSymbolAddress((void**)&h2, g_h2);

    // gx = x @ w_ih^T + b_ih + b_hh : [2048, 4096]
    sgemm_bt<<<dim3(G4 / 64, SEQT / 64), 256>>>(x, w_ih, b_ih, b_hh, gx,
                                                SEQT, G4, INSZ, 0);
    // reset arrival counter (same stream: ordered, graph-capturable)
    reset_kernel<<<1, 1>>>();
    // recurrence (persistent; also writes hT, cT into out)
    lstm_kernel<<<LSTM_BLOCKS, 256>>>(gx, w_hh, h0, c0, ys, out);
    // fc1, fc2 with ReLU
    sgemm_bt<<<dim3(HID / 64, SEQT / 64), 256>>>(ys, fc1_w, fc1_b, nullptr, h1,
                                                 SEQT, HID, HID, 1);
    sgemm_bt<<<dim3(HID / 64, SEQT / 64), 256>>>(h1, fc2_w, fc2_b, nullptr, h2,
                                                 SEQT, HID, HID, 1);
    // head: action_mean + action_log_std
    head_kernel<<<SEQT, 128>>>(h2, mean_w, mean_b, lstd, out);
}

// round 11
// speedup vs baseline: 1.2846x; 1.2846x over previous
#include <cuda_runtime.h>
#include <math.h>

#define SEQT 2048
#define INSZ 512
#define HID  1024
#define G4   4096   // 4*HID
#define OUTD 4

// ---------------- scratch (static device allocations only) ----------------
__device__ float g_gx[SEQT * G4];        // 32 MB: input projections + biases
__device__ float g_ys[SEQT * HID];       // 8 MB: LSTM outputs
__device__ float g_h1[SEQT * HID];       // 8 MB
__device__ float g_h2[SEQT * HID];       // 8 MB
__device__ float g_hbuf[2][HID];         // double-buffered recurrent state
#define LSTM_BLOCKS 128
__device__ int g_flag[LSTM_BLOCKS * 32]; // per-block step flags, one 128B line each

// ---------------- tiled SGEMM: C[M,N] = A[M,K] @ B[N,K]^T + bias (+bias2), opt ReLU
__global__ void __launch_bounds__(256) sgemm_bt(
    const float* __restrict__ A, const float* __restrict__ B,
    const float* __restrict__ bias, const float* __restrict__ bias2,
    float* __restrict__ C, int M, int N, int K, int relu)
{
    __shared__ float As[16][64];
    __shared__ float Bs[16][64];
    int tid = threadIdx.x;
    int tx = tid & 15, ty = tid >> 4;
    int m0 = blockIdx.y * 64, n0 = blockIdx.x * 64;

    int lm  = tid >> 2;
    int lk4 = tid & 3;

    const float4* Ag = (const float4*)(A + (size_t)(m0 + lm) * K) + lk4;
    const float4* Bg = (const float4*)(B + (size_t)(n0 + lm) * K) + lk4;

    float acc[4][4] = {};

    for (int k0 = 0; k0 < K; k0 += 16) {
        float4 av = *Ag; Ag += 4;
        float4 bv = *Bg; Bg += 4;
        __syncthreads();
        As[lk4 * 4 + 0][lm] = av.x; As[lk4 * 4 + 1][lm] = av.y;
        As[lk4 * 4 + 2][lm] = av.z; As[lk4 * 4 + 3][lm] = av.w;
        Bs[lk4 * 4 + 0][lm] = bv.x; Bs[lk4 * 4 + 1][lm] = bv.y;
        Bs[lk4 * 4 + 2][lm] = bv.z; Bs[lk4 * 4 + 3][lm] = bv.w;
        __syncthreads();
        #pragma unroll
        for (int k = 0; k < 16; k++) {
            float4 a4 = *(const float4*)&As[k][ty * 4];
            float4 b4 = *(const float4*)&Bs[k][tx * 4];
            float a_[4] = {a4.x, a4.y, a4.z, a4.w};
            float b_[4] = {b4.x, b4.y, b4.z, b4.w};
            #pragma unroll
            for (int i = 0; i < 4; i++)
                #pragma unroll
                for (int j = 0; j < 4; j++)
                    acc[i][j] = fmaf(a_[i], b_[j], acc[i][j]);
        }
    }

    int n = n0 + tx * 4;
    float bb[4];
    #pragma unroll
    for (int j = 0; j < 4; j++) {
        bb[j] = bias ? bias[n + j] : 0.f;
        if (bias2) bb[j] += bias2[n + j];
    }
    #pragma unroll
    for (int i = 0; i < 4; i++) {
        int m = m0 + ty * 4 + i;
        float4 r;
        r.x = acc[i][0] + bb[0];
        r.y = acc[i][1] + bb[1];
        r.z = acc[i][2] + bb[2];
        r.w = acc[i][3] + bb[3];
        if (relu) {
            r.x = fmaxf(r.x, 0.f); r.y = fmaxf(r.y, 0.f);
            r.z = fmaxf(r.z, 0.f); r.w = fmaxf(r.w, 0.f);
        }
        *(float4*)&C[(size_t)m * N + n] = r;
    }
}

// ---------------- sync helpers ----------------
__device__ __forceinline__ int ld_acq_gpu_i(const int* p)
{
    int v;
    asm volatile("ld.acquire.gpu.global.s32 %0, [%1];" : "=r"(v) : "l"(p) : "memory");
    return v;
}

__device__ __forceinline__ void st_rel_gpu_i(int* p, int v)
{
    asm volatile("st.release.gpu.global.s32 [%0], %1;" :: "l"(p), "r"(v) : "memory");
}

__device__ __forceinline__ float tanh_approx(float x)
{
    float r;
    asm("tanh.approx.f32 %0, %1;" : "=f"(r) : "f"(x));
    return r;
}

__device__ __forceinline__ float sigmoidf_(float x) { return 1.f / (1.f + __expf(-x)); }

__global__ void reset_kernel()
{
    g_flag[threadIdx.x * 32] = 0;
}

// ---------------- persistent LSTM recurrence ----------------
// grid = 128 blocks x 256 threads (8 warps). Warp w of block b owns hidden unit
// hu = 8b + w, computing all 4 gate rows. Lane l covers k-slice {l+32i, i=0..7}
// (float4 granularity): h read from SHARED once per lane (8 LDS.128), reused
// across the 4 gate rows; weights are L1-resident (128KB/SM).
// Sync: per-block flag on its own 128B line. flag[b] == t+1  <=>  block b has
// produced its slice of h(t) (in g_hbuf[t&1]). Threads 0..127 of each block
// poll one flag each with ld.acquire and immediately stage that producer's
// 8-float chunk into shared — no atomics, no shared hot address.
__global__ void __launch_bounds__(256, 1) lstm_kernel(
    const float* __restrict__ gx, const float* __restrict__ w_hh,
    const float* __restrict__ h0, const float* __restrict__ c0,
    float* __restrict__ ys, float* __restrict__ out)
{
    __shared__ float sh[HID];
    int tid  = threadIdx.x;
    int warp = tid >> 5, lane = tid & 31;
    int hu   = blockIdx.x * 8 + warp;          // 0..1023

    const float4* w0 = (const float4*)(w_hh + (size_t)(0 * HID + hu) * HID) + lane;
    const float4* w1 = (const float4*)(w_hh + (size_t)(1 * HID + hu) * HID) + lane;
    const float4* w2 = (const float4*)(w_hh + (size_t)(2 * HID + hu) * HID) + lane;
    const float4* w3 = (const float4*)(w_hh + (size_t)(3 * HID + hu) * HID) + lane;
    const float*  gxp = gx + (size_t)(lane & 3) * HID + hu;   // lanes 0..3: 4 gate values

    int* myflag = &g_flag[blockIdx.x * 32];

    float c = c0[hu];
    float hlast = h0[hu];
    // produce h(0) slice
    if (lane == 0) __stcg(&g_hbuf[0][hu], hlast);
    __syncthreads();
    if (tid == 0) st_rel_gpu_i(myflag, 1);

    for (int t = 0; t < SEQT; t++) {
        float*       hbn = g_hbuf[(t & 1) ^ 1];
        const float2* hb2 = (const float2*)g_hbuf[t & 1];

        // prefetch this step's gx gate values (independent of other blocks)
        float gxv = 0.f;
        if (lane < 4) gxv = __ldcs(gxp + (size_t)t * G4);

        // threads 0..127: poll producer j's flag, then stage its 8-float chunk
        if (tid < LSTM_BLOCKS) {
            const int* fl = &g_flag[tid * 32];
            int target = t + 1;
            while (ld_acq_gpu_i(fl) < target) { }
            float2 v0 = __ldcg(hb2 + tid * 4 + 0);
            float2 v1 = __ldcg(hb2 + tid * 4 + 1);
            float2 v2 = __ldcg(hb2 + tid * 4 + 2);
            float2 v3 = __ldcg(hb2 + tid * 4 + 3);
            float2* s2 = (float2*)sh + tid * 4;
            s2[0] = v0; s2[1] = v1; s2[2] = v2; s2[3] = v3;
        }
        __syncthreads();

        // dot products: lane l covers float4 indices {l+32i}, reused for 4 rows
        const float4* h4 = (const float4*)sh;
        float a0 = 0.f, a1 = 0.f, a2 = 0.f, a3 = 0.f;
        #pragma unroll
        for (int i = 0; i < 8; i++) {
            float4 x  = h4[lane + (i << 5)];
            float4 u0 = __ldg(w0 + (i << 5));
            float4 u1 = __ldg(w1 + (i << 5));
            float4 u2 = __ldg(w2 + (i << 5));
            float4 u3 = __ldg(w3 + (i << 5));
            a0 = fmaf(u0.x, x.x, a0); a0 = fmaf(u0.y, x.y, a0);
            a0 = fmaf(u0.z, x.z, a0); a0 = fmaf(u0.w, x.w, a0);
            a1 = fmaf(u1.x, x.x, a1); a1 = fmaf(u1.y, x.y, a1);
            a1 = fmaf(u1.z, x.z, a1); a1 = fmaf(u1.w, x.w, a1);
            a2 = fmaf(u2.x, x.x, a2); a2 = fmaf(u2.y, x.y, a2);
            a2 = fmaf(u2.z, x.z, a2); a2 = fmaf(u2.w, x.w, a2);
            a3 = fmaf(u3.x, x.x, a3); a3 = fmaf(u3.y, x.y, a3);
            a3 = fmaf(u3.z, x.z, a3); a3 = fmaf(u3.w, x.w, a3);
        }

        // 4 interleaved warp reductions -> lane 0 has all 4 gate sums
        #pragma unroll
        for (int off = 16; off; off >>= 1) {
            a0 += __shfl_down_sync(0xffffffffu, a0, off);
            a1 += __shfl_down_sync(0xffffffffu, a1, off);
            a2 += __shfl_down_sync(0xffffffffu, a2, off);
            a3 += __shfl_down_sync(0xffffffffu, a3, off);
        }
        float gx_i = __shfl_sync(0xffffffffu, gxv, 0);
        float gx_f = __shfl_sync(0xffffffffu, gxv, 1);
        float gx_g = __shfl_sync(0xffffffffu, gxv, 2);
        float gx_o = __shfl_sync(0xffffffffu, gxv, 3);

        if (lane == 0) {
            float i_ = sigmoidf_(a0 + gx_i);
            float f_ = sigmoidf_(a1 + gx_f);
            float g_ = tanh_approx(a2 + gx_g);
            float o_ = sigmoidf_(a3 + gx_o);
            c = fmaf(f_, c, i_ * g_);
            float h = o_ * tanh_approx(c);
            hlast = h;
            __stcg(&hbn[hu], h);
            __stcs(&ys[(size_t)t * HID + hu], h);
        }
        __syncthreads();                      // all 8 h writes of this block done
        if (tid == 0) st_rel_gpu_i(myflag, t + 2);
    }

    // hT at out[16384..17407], cT at out[17408..18431]
    if (lane == 0) {
        out[2 * SEQT * OUTD + hu] = hlast;
        out[2 * SEQT * OUTD + HID + hu] = c;
    }
}

// ---------------- policy head ----------------
__global__ void __launch_bounds__(128) head_kernel(
    const float* __restrict__ h2, const float* __restrict__ mean_w,
    const float* __restrict__ mean_b, const float* __restrict__ log_std,
    float* __restrict__ out)
{
    __shared__ float sh[HID];
    int t = blockIdx.x;
    for (int i = threadIdx.x; i < HID; i += 128) sh[i] = h2[(size_t)t * HID + i];
    __syncthreads();
    int w = threadIdx.x >> 5, lane = threadIdx.x & 31;
    const float* wr = mean_w + (size_t)w * HID;
    float acc = 0.f;
    for (int k = lane; k < HID; k += 32) acc = fmaf(wr[k], sh[k], acc);
    #pragma unroll
    for (int o = 16; o; o >>= 1) acc += __shfl_down_sync(0xffffffffu, acc, o);
    if (lane == 0) {
        out[(size_t)t * OUTD + w] = acc + mean_b[w];
        out[SEQT * OUTD + (size_t)t * OUTD + w] = log_std[w];
    }
}

// ---------------- launcher ----------------
extern "C" void kernel_launch(void* const* d_in, const int* in_sizes, int n_in,
                              void* d_out, int out_size)
{
    const float* x      = (const float*)d_in[0];
    const float* h0     = (const float*)d_in[1];
    const float* c0     = (const float*)d_in[2];
    const float* w_ih   = (const float*)d_in[3];
    const float* w_hh   = (const float*)d_in[4];
    const float* b_ih   = (const float*)d_in[5];
    const float* b_hh   = (const float*)d_in[6];
    const float* fc1_w  = (const float*)d_in[7];
    const float* fc1_b  = (const float*)d_in[8];
    const float* fc2_w  = (const float*)d_in[9];
    const float* fc2_b  = (const float*)d_in[10];
    const float* mean_w = (const float*)d_in[11];
    const float* mean_b = (const float*)d_in[12];
    const float* lstd   = (const float*)d_in[13];
    float* out = (float*)d_out;

    float *gx, *ys, *h1, *h2;
    cudaGetSymbolAddress((void**)&gx, g_gx);
    cudaGetSymbolAddress((void**)&ys, g_ys);
    cudaGetSymbolAddress((void**)&h1, g_h1);
    cudaGetSymbolAddress((void**)&h2, g_h2);

    // gx = x @ w_ih^T + b_ih + b_hh : [2048, 4096]
    sgemm_bt<<<dim3(G4 / 64, SEQT / 64), 256>>>(x, w_ih, b_ih, b_hh, gx,
                                                SEQT, G4, INSZ, 0);
    // reset per-block flags (same stream: ordered, graph-capturable)
    reset_kernel<<<1, LSTM_BLOCKS>>>();
    // recurrence (persistent; also writes hT, cT into out)
    lstm_kernel<<<LSTM_BLOCKS, 256>>>(gx, w_hh, h0, c0, ys, out);
    // fc1, fc2 with ReLU
    sgemm_bt<<<dim3(HID / 64, SEQT / 64), 256>>>(ys, fc1_w, fc1_b, nullptr, h1,
                                                 SEQT, HID, HID, 1);
    sgemm_bt<<<dim3(HID / 64, SEQT / 64), 256>>>(h1, fc2_w, fc2_b, nullptr, h2,
                                                 SEQT, HID, HID, 1);
    // head: action_mean + action_log_std
    head_kernel<<<SEQT, 128>>>(h2, mean_w, mean_b, lstd, out);
}

// round 12
// speedup vs baseline: 1.4872x; 1.1577x over previous
#include <cuda_runtime.h>
#include <math.h>

#define SEQT 2048
#define INSZ 512
#define HID  1024
#define G4   4096   // 4*HID
#define OUTD 4

// ---------------- scratch (static device allocations only) ----------------
__device__ float g_gx[SEQT * G4];     // 32 MB: input projections + biases
__device__ float g_ys[SEQT * HID];    // 8 MB: LSTM outputs
__device__ float g_h1[SEQT * HID];    // 8 MB
__device__ float g_h2[SEQT * HID];    // 8 MB
__device__ float g_hbuf[2][HID];      // double-buffered recurrent state
__device__ unsigned g_arrive;         // monotonic arrival counter (reset each launch)

// ---------------- tiled SGEMM: C[M,N] = A[M,K] @ B[N,K]^T + bias (+bias2), opt ReLU
__global__ void __launch_bounds__(256) sgemm_bt(
    const float* __restrict__ A, const float* __restrict__ B,
    const float* __restrict__ bias, const float* __restrict__ bias2,
    float* __restrict__ C, int M, int N, int K, int relu)
{
    __shared__ float As[16][64];
    __shared__ float Bs[16][64];
    int tid = threadIdx.x;
    int tx = tid & 15, ty = tid >> 4;
    int m0 = blockIdx.y * 64, n0 = blockIdx.x * 64;

    int lm  = tid >> 2;
    int lk4 = tid & 3;

    const float4* Ag = (const float4*)(A + (size_t)(m0 + lm) * K) + lk4;
    const float4* Bg = (const float4*)(B + (size_t)(n0 + lm) * K) + lk4;

    float acc[4][4] = {};

    for (int k0 = 0; k0 < K; k0 += 16) {
        float4 av = *Ag; Ag += 4;
        float4 bv = *Bg; Bg += 4;
        __syncthreads();
        As[lk4 * 4 + 0][lm] = av.x; As[lk4 * 4 + 1][lm] = av.y;
        As[lk4 * 4 + 2][lm] = av.z; As[lk4 * 4 + 3][lm] = av.w;
        Bs[lk4 * 4 + 0][lm] = bv.x; Bs[lk4 * 4 + 1][lm] = bv.y;
        Bs[lk4 * 4 + 2][lm] = bv.z; Bs[lk4 * 4 + 3][lm] = bv.w;
        __syncthreads();
        #pragma unroll
        for (int k = 0; k < 16; k++) {
            float4 a4 = *(const float4*)&As[k][ty * 4];
            float4 b4 = *(const float4*)&Bs[k][tx * 4];
            float a_[4] = {a4.x, a4.y, a4.z, a4.w};
            float b_[4] = {b4.x, b4.y, b4.z, b4.w};
            #pragma unroll
            for (int i = 0; i < 4; i++)
                #pragma unroll
                for (int j = 0; j < 4; j++)
                    acc[i][j] = fmaf(a_[i], b_[j], acc[i][j]);
        }
    }

    int n = n0 + tx * 4;
    float bb[4];
    #pragma unroll
    for (int j = 0; j < 4; j++) {
        bb[j] = bias ? bias[n + j] : 0.f;
        if (bias2) bb[j] += bias2[n + j];
    }
    #pragma unroll
    for (int i = 0; i < 4; i++) {
        int m = m0 + ty * 4 + i;
        float4 r;
        r.x = acc[i][0] + bb[0];
        r.y = acc[i][1] + bb[1];
        r.z = acc[i][2] + bb[2];
        r.w = acc[i][3] + bb[3];
        if (relu) {
            r.x = fmaxf(r.x, 0.f); r.y = fmaxf(r.y, 0.f);
            r.z = fmaxf(r.z, 0.f); r.w = fmaxf(r.w, 0.f);
        }
        *(float4*)&C[(size_t)m * N + n] = r;
    }
}

// ---------------- sync helpers ----------------
__device__ __forceinline__ unsigned ld_acq_gpu(const unsigned* p)
{
    unsigned v;
    asm volatile("ld.acquire.gpu.global.u32 %0, [%1];" : "=r"(v) : "l"(p) : "memory");
    return v;
}

__device__ __forceinline__ void red_release_add(unsigned* p, unsigned v)
{
    asm volatile("red.release.gpu.global.add.u32 [%0], %1;" :: "l"(p), "r"(v) : "memory");
}

__device__ __forceinline__ float tanh_approx(float x)
{
    float r;
    asm("tanh.approx.f32 %0, %1;" : "=f"(r) : "f"(x));
    return r;
}

__device__ __forceinline__ float sigmoidf_(float x) { return 1.f / (1.f + __expf(-x)); }

__global__ void reset_kernel() { g_arrive = 0u; }

// ---------------- persistent LSTM recurrence ----------------
// grid = 128 blocks x 256 threads (8 warps). Warp w of block b owns hidden unit
// hu = 8b + w, computing all 4 gate rows. Sync (R5 scheme, best measured):
// single global counter; producer blocks red.release-add after writing their
// h slice; ONE poller thread per block ld.acquire-polls (read-broadcast line).
// Matvec: h staged to shared once (256 x float4), then lane l covers k-slice
// {l+32i, i=0..7}: 8 LDS.128 per lane, reused across all 4 gate rows.
// Epilogue: butterfly reductions give all lanes the 4 sums; lanes 0..3 compute
// the 4 activations in parallel.
#define LSTM_BLOCKS 128
__global__ void __launch_bounds__(256, 1) lstm_kernel(
    const float* __restrict__ gx, const float* __restrict__ w_hh,
    const float* __restrict__ h0, const float* __restrict__ c0,
    float* __restrict__ ys, float* __restrict__ out)
{
    __shared__ float sh[HID];
    int tid  = threadIdx.x;
    int warp = tid >> 5, lane = tid & 31;
    int hu   = blockIdx.x * 8 + warp;          // 0..1023

    const float4* w0 = (const float4*)(w_hh + (size_t)(0 * HID + hu) * HID) + lane;
    const float4* w1 = (const float4*)(w_hh + (size_t)(1 * HID + hu) * HID) + lane;
    const float4* w2 = (const float4*)(w_hh + (size_t)(2 * HID + hu) * HID) + lane;
    const float4* w3 = (const float4*)(w_hh + (size_t)(3 * HID + hu) * HID) + lane;
    const float*  gxp = gx + (size_t)(lane & 3) * HID + hu;   // lanes 0..3: i,f,g,o

    float c = c0[hu];
    float hlast = h0[hu];
    if (lane == 0) __stcg(&g_hbuf[0][hu], hlast);
    __syncthreads();
    if (tid == 0) red_release_add(&g_arrive, 1u);

    for (int t = 0; t < SEQT; t++) {
        const float4* hb  = (const float4*)g_hbuf[t & 1];
        float*        hbn = g_hbuf[(t & 1) ^ 1];

        // prefetch this step's gx gate values (independent of other blocks)
        float gxv = 0.f;
        if (lane < 4) gxv = __ldcs(gxp + (size_t)t * G4);

        // single poller per block on the (read-broadcast) counter line
        if (tid == 0) {
            unsigned target = (unsigned)(LSTM_BLOCKS * (t + 1));
            while (ld_acq_gpu(&g_arrive) < target) { }
        }
        __syncthreads();

        // stage h(t) into shared: 256 threads x float4 = 4KB in one round
        ((float4*)sh)[tid] = __ldcg(hb + tid);
        __syncthreads();

        // dot products: lane l covers float4 indices {l+32i}, reused for 4 rows
        const float4* h4 = (const float4*)sh;
        float a0 = 0.f, a1 = 0.f, a2 = 0.f, a3 = 0.f;
        #pragma unroll
        for (int i = 0; i < 8; i++) {
            float4 x  = h4[lane + (i << 5)];
            float4 u0 = __ldg(w0 + (i << 5));
            float4 u1 = __ldg(w1 + (i << 5));
            float4 u2 = __ldg(w2 + (i << 5));
            float4 u3 = __ldg(w3 + (i << 5));
            a0 = fmaf(u0.x, x.x, a0); a0 = fmaf(u0.y, x.y, a0);
            a0 = fmaf(u0.z, x.z, a0); a0 = fmaf(u0.w, x.w, a0);
            a1 = fmaf(u1.x, x.x, a1); a1 = fmaf(u1.y, x.y, a1);
            a1 = fmaf(u1.z, x.z, a1); a1 = fmaf(u1.w, x.w, a1);
            a2 = fmaf(u2.x, x.x, a2); a2 = fmaf(u2.y, x.y, a2);
            a2 = fmaf(u2.z, x.z, a2); a2 = fmaf(u2.w, x.w, a2);
            a3 = fmaf(u3.x, x.x, a3); a3 = fmaf(u3.y, x.y, a3);
            a3 = fmaf(u3.z, x.z, a3); a3 = fmaf(u3.w, x.w, a3);
        }

        // butterfly reductions: ALL lanes end with the 4 full sums
        #pragma unroll
        for (int off = 16; off; off >>= 1) {
            a0 += __shfl_xor_sync(0xffffffffu, a0, off);
            a1 += __shfl_xor_sync(0xffffffffu, a1, off);
            a2 += __shfl_xor_sync(0xffffffffu, a2, off);
            a3 += __shfl_xor_sync(0xffffffffu, a3, off);
        }

        // activations in parallel on lanes 0..3 (lane l owns gate l; gxv is its gate's gx)
        float pre = ((lane == 0) ? a0 : (lane == 1) ? a1 : (lane == 2) ? a2 : a3) + gxv;
        float act = 0.f;
        if (lane < 4) act = (lane == 2) ? tanh_approx(pre) : sigmoidf_(pre);
        float i_ = __shfl_sync(0xffffffffu, act, 0);
        float f_ = __shfl_sync(0xffffffffu, act, 1);
        float g_ = __shfl_sync(0xffffffffu, act, 2);
        float o_ = __shfl_sync(0xffffffffu, act, 3);

        if (lane == 0) {
            c = fmaf(f_, c, i_ * g_);
            float h = o_ * tanh_approx(c);
            hlast = h;
            __stcg(&hbn[hu], h);
            __stcs(&ys[(size_t)t * HID + hu], h);
        }
        __syncthreads();                      // all 8 h writes of this block done
        if (tid == 0) red_release_add(&g_arrive, 1u);
    }

    // hT at out[16384..17407], cT at out[17408..18431]
    if (lane == 0) {
        out[2 * SEQT * OUTD + hu] = hlast;
        out[2 * SEQT * OUTD + HID + hu] = c;
    }
}

// ---------------- policy head ----------------
__global__ void __launch_bounds__(128) head_kernel(
    const float* __restrict__ h2, const float* __restrict__ mean_w,
    const float* __restrict__ mean_b, const float* __restrict__ log_std,
    float* __restrict__ out)
{
    __shared__ float sh[HID];
    int t = blockIdx.x;
    for (int i = threadIdx.x; i < HID; i += 128) sh[i] = h2[(size_t)t * HID + i];
    __syncthreads();
    int w = threadIdx.x >> 5, lane = threadIdx.x & 31;
    const float* wr = mean_w + (size_t)w * HID;
    float acc = 0.f;
    for (int k = lane; k < HID; k += 32) acc = fmaf(wr[k], sh[k], acc);
    #pragma unroll
    for (int o = 16; o; o >>= 1) acc += __shfl_down_sync(0xffffffffu, acc, o);
    if (lane == 0) {
        out[(size_t)t * OUTD + w] = acc + mean_b[w];
        out[SEQT * OUTD + (size_t)t * OUTD + w] = log_std[w];
    }
}

// ---------------- launcher ----------------
extern "C" void kernel_launch(void* const* d_in, const int* in_sizes, int n_in,
                              void* d_out, int out_size)
{
    const float* x      = (const float*)d_in[0];
    const float* h0     = (const float*)d_in[1];
    const float* c0     = (const float*)d_in[2];
    const float* w_ih   = (const float*)d_in[3];
    const float* w_hh   = (const float*)d_in[4];
    const float* b_ih   = (const float*)d_in[5];
    const float* b_hh   = (const float*)d_in[6];
    const float* fc1_w  = (const float*)d_in[7];
    const float* fc1_b  = (const float*)d_in[8];
    const float* fc2_w  = (const float*)d_in[9];
    const float* fc2_b  = (const float*)d_in[10];
    const float* mean_w = (const float*)d_in[11];
    const float* mean_b = (const float*)d_in[12];
    const float* lstd   = (const float*)d_in[13];
    float* out = (float*)d_out;

    float *gx, *ys, *h1, *h2;
    cudaGetSymbolAddress((void**)&gx, g_gx);
    cudaGetSymbolAddress((void**)&ys, g_ys);
    cudaGetSymbolAddress((void**)&h1, g_h1);
    cudaGetSymbolAddress((void**)&h2, g_h2);

    // gx = x @ w_ih^T + b_ih + b_hh : [2048, 4096]
    sgemm_bt<<<dim3(G4 / 64, SEQT / 64), 256>>>(x, w_ih, b_ih, b_hh, gx,
                                                SEQT, G4, INSZ, 0);
    // reset arrival counter (same stream: ordered, graph-capturable)
    reset_kernel<<<1, 1>>>();
    // recurrence (persistent; also writes hT, cT into out)
    lstm_kernel<<<LSTM_BLOCKS, 256>>>(gx, w_hh, h0, c0, ys, out);
    // fc1, fc2 with ReLU
    sgemm_bt<<<dim3(HID / 64, SEQT / 64), 256>>>(ys, fc1_w, fc1_b, nullptr, h1,
                                                 SEQT, HID, HID, 1);
    sgemm_bt<<<dim3(HID / 64, SEQT / 64), 256>>>(h1, fc2_w, fc2_b, nullptr, h2,
                                                 SEQT, HID, HID, 1);
    // head: action_mean + action_log_std
    head_kernel<<<SEQT, 128>>>(h2, mean_w, mean_b, lstd, out);
}

// round 13
// speedup vs baseline: 2.0142x; 1.3544x over previous
#include <cuda_runtime.h>
#include <math.h>

#define SEQT 2048
#define INSZ 512
#define HID  1024
#define G4   4096   // 4*HID
#define OUTD 4

// ---------------- scratch (static device allocations only) ----------------
__device__ float g_gx[SEQT * G4];     // 32 MB: input projections + biases
__device__ float g_ys[SEQT * HID];    // 8 MB: LSTM outputs
__device__ float g_h1[SEQT * HID];    // 8 MB
__device__ float g_h2[SEQT * HID];    // 8 MB
__device__ float g_hbuf[2][HID];      // double-buffered recurrent state
__device__ unsigned g_arrive;         // monotonic arrival counter (reset each launch)

// ---------------- tiled SGEMM: C[M,N] = A[M,K] @ B[N,K]^T + bias (+bias2), opt ReLU
__global__ void __launch_bounds__(256) sgemm_bt(
    const float* __restrict__ A, const float* __restrict__ B,
    const float* __restrict__ bias, const float* __restrict__ bias2,
    float* __restrict__ C, int M, int N, int K, int relu)
{
    __shared__ float As[16][64];
    __shared__ float Bs[16][64];
    int tid = threadIdx.x;
    int tx = tid & 15, ty = tid >> 4;
    int m0 = blockIdx.y * 64, n0 = blockIdx.x * 64;

    int lm  = tid >> 2;
    int lk4 = tid & 3;

    const float4* Ag = (const float4*)(A + (size_t)(m0 + lm) * K) + lk4;
    const float4* Bg = (const float4*)(B + (size_t)(n0 + lm) * K) + lk4;

    float acc[4][4] = {};

    for (int k0 = 0; k0 < K; k0 += 16) {
        float4 av = *Ag; Ag += 4;
        float4 bv = *Bg; Bg += 4;
        __syncthreads();
        As[lk4 * 4 + 0][lm] = av.x; As[lk4 * 4 + 1][lm] = av.y;
        As[lk4 * 4 + 2][lm] = av.z; As[lk4 * 4 + 3][lm] = av.w;
        Bs[lk4 * 4 + 0][lm] = bv.x; Bs[lk4 * 4 + 1][lm] = bv.y;
        Bs[lk4 * 4 + 2][lm] = bv.z; Bs[lk4 * 4 + 3][lm] = bv.w;
        __syncthreads();
        #pragma unroll
        for (int k = 0; k < 16; k++) {
            float4 a4 = *(const float4*)&As[k][ty * 4];
            float4 b4 = *(const float4*)&Bs[k][tx * 4];
            float a_[4] = {a4.x, a4.y, a4.z, a4.w};
            float b_[4] = {b4.x, b4.y, b4.z, b4.w};
            #pragma unroll
            for (int i = 0; i < 4; i++)
                #pragma unroll
                for (int j = 0; j < 4; j++)
                    acc[i][j] = fmaf(a_[i], b_[j], acc[i][j]);
        }
    }

    int n = n0 + tx * 4;
    float bb[4];
    #pragma unroll
    for (int j = 0; j < 4; j++) {
        bb[j] = bias ? bias[n + j] : 0.f;
        if (bias2) bb[j] += bias2[n + j];
    }
    #pragma unroll
    for (int i = 0; i < 4; i++) {
        int m = m0 + ty * 4 + i;
        float4 r;
        r.x = acc[i][0] + bb[0];
        r.y = acc[i][1] + bb[1];
        r.z = acc[i][2] + bb[2];
        r.w = acc[i][3] + bb[3];
        if (relu) {
            r.x = fmaxf(r.x, 0.f); r.y = fmaxf(r.y, 0.f);
            r.z = fmaxf(r.z, 0.f); r.w = fmaxf(r.w, 0.f);
        }
        *(float4*)&C[(size_t)m * N + n] = r;
    }
}

// ---------------- sync helpers ----------------
__device__ __forceinline__ unsigned ld_acq_gpu(const unsigned* p)
{
    unsigned v;
    asm volatile("ld.acquire.gpu.global.u32 %0, [%1];" : "=r"(v) : "l"(p) : "memory");
    return v;
}

__device__ __forceinline__ void red_release_add(unsigned* p, unsigned v)
{
    asm volatile("red.release.gpu.global.add.u32 [%0], %1;" :: "l"(p), "r"(v) : "memory");
}

__device__ __forceinline__ float tanh_approx(float x)
{
    float r;
    asm("tanh.approx.f32 %0, %1;" : "=f"(r) : "f"(x));
    return r;
}

__device__ __forceinline__ float sigmoidf_(float x) { return 1.f / (1.f + __expf(-x)); }

__global__ void reset_kernel() { g_arrive = 0u; }

// ---------------- persistent LSTM recurrence ----------------
// grid = 128 blocks x 256 threads (8 warps), 1 block/SM. Warp w of block b owns
// hidden unit hu = 8b + w, computing all 4 gate rows.
// WEIGHTS LIVE IN REGISTERS: lane l holds w_hh[{i,f,g,o} row of hu][l+32i slices]
// = 4 rows x 8 float4 = 128 floats, loaded ONCE before the t-loop (persistent
// kernel, occupancy 1 by design). The per-step loop has zero weight traffic:
// poll -> stage h to shared -> LDS + register FFMA -> butterfly reduce -> act.
// Sync (best measured): single global counter, red.release arrive per block,
// one acquire-poller per block on a read-broadcast line.
#define LSTM_BLOCKS 128
__global__ void __launch_bounds__(256, 1) lstm_kernel(
    const float* __restrict__ gx, const float* __restrict__ w_hh,
    const float* __restrict__ h0, const float* __restrict__ c0,
    float* __restrict__ ys, float* __restrict__ out)
{
    __shared__ float sh[HID];
    int tid  = threadIdx.x;
    int warp = tid >> 5, lane = tid & 31;
    int hu   = blockIdx.x * 8 + warp;          // 0..1023

    // hoist weights into registers: wr[row][i] = w_hh[row*HID+hu][ (lane+32i)*4 .. +3 ]
    float4 wr0[8], wr1[8], wr2[8], wr3[8];
    {
        const float4* p0 = (const float4*)(w_hh + (size_t)(0 * HID + hu) * HID) + lane;
        const float4* p1 = (const float4*)(w_hh + (size_t)(1 * HID + hu) * HID) + lane;
        const float4* p2 = (const float4*)(w_hh + (size_t)(2 * HID + hu) * HID) + lane;
        const float4* p3 = (const float4*)(w_hh + (size_t)(3 * HID + hu) * HID) + lane;
        #pragma unroll
        for (int i = 0; i < 8; i++) {
            wr0[i] = p0[i << 5];
            wr1[i] = p1[i << 5];
            wr2[i] = p2[i << 5];
            wr3[i] = p3[i << 5];
        }
    }
    const float* gxp = gx + (size_t)(lane & 3) * HID + hu;   // lanes 0..3: i,f,g,o

    float c = c0[hu];
    float hlast = h0[hu];
    if (lane == 0) __stcg(&g_hbuf[0][hu], hlast);
    __syncthreads();
    if (tid == 0) red_release_add(&g_arrive, 1u);

    for (int t = 0; t < SEQT; t++) {
        const float4* hb  = (const float4*)g_hbuf[t & 1];
        float*        hbn = g_hbuf[(t & 1) ^ 1];

        // prefetch this step's gx gate values (independent of other blocks)
        float gxv = 0.f;
        if (lane < 4) gxv = __ldcs(gxp + (size_t)t * G4);

        // single poller per block on the (read-broadcast) counter line
        if (tid == 0) {
            unsigned target = (unsigned)(LSTM_BLOCKS * (t + 1));
            while (ld_acq_gpu(&g_arrive) < target) { }
        }
        __syncthreads();

        // stage h(t) into shared: 256 threads x float4 = 4KB in one round
        ((float4*)sh)[tid] = __ldcg(hb + tid);
        __syncthreads();

        // dot products: lane l covers float4 indices {l+32i}; weights in regs
        const float4* h4 = (const float4*)sh;
        float a0 = 0.f, a1 = 0.f, a2 = 0.f, a3 = 0.f;
        #pragma unroll
        for (int i = 0; i < 8; i++) {
            float4 x = h4[lane + (i << 5)];
            a0 = fmaf(wr0[i].x, x.x, a0); a0 = fmaf(wr0[i].y, x.y, a0);
            a0 = fmaf(wr0[i].z, x.z, a0); a0 = fmaf(wr0[i].w, x.w, a0);
            a1 = fmaf(wr1[i].x, x.x, a1); a1 = fmaf(wr1[i].y, x.y, a1);
            a1 = fmaf(wr1[i].z, x.z, a1); a1 = fmaf(wr1[i].w, x.w, a1);
            a2 = fmaf(wr2[i].x, x.x, a2); a2 = fmaf(wr2[i].y, x.y, a2);
            a2 = fmaf(wr2[i].z, x.z, a2); a2 = fmaf(wr2[i].w, x.w, a2);
            a3 = fmaf(wr3[i].x, x.x, a3); a3 = fmaf(wr3[i].y, x.y, a3);
            a3 = fmaf(wr3[i].z, x.z, a3); a3 = fmaf(wr3[i].w, x.w, a3);
        }

        // butterfly reductions: ALL lanes end with the 4 full sums
        #pragma unroll
        for (int off = 16; off; off >>= 1) {
            a0 += __shfl_xor_sync(0xffffffffu, a0, off);
            a1 += __shfl_xor_sync(0xffffffffu, a1, off);
            a2 += __shfl_xor_sync(0xffffffffu, a2, off);
            a3 += __shfl_xor_sync(0xffffffffu, a3, off);
        }

        // activations in parallel on lanes 0..3 (lane l owns gate l)
        float pre = ((lane == 0) ? a0 : (lane == 1) ? a1 : (lane == 2) ? a2 : a3) + gxv;
        float act = 0.f;
        if (lane < 4) act = (lane == 2) ? tanh_approx(pre) : sigmoidf_(pre);
        float i_ = __shfl_sync(0xffffffffu, act, 0);
        float f_ = __shfl_sync(0xffffffffu, act, 1);
        float g_ = __shfl_sync(0xffffffffu, act, 2);
        float o_ = __shfl_sync(0xffffffffu, act, 3);

        if (lane == 0) {
            c = fmaf(f_, c, i_ * g_);
            float h = o_ * tanh_approx(c);
            hlast = h;
            __stcg(&hbn[hu], h);
            __stcs(&ys[(size_t)t * HID + hu], h);
        }
        __syncthreads();                      // all 8 h writes of this block done
        if (tid == 0) red_release_add(&g_arrive, 1u);
    }

    // hT at out[16384..17407], cT at out[17408..18431]
    if (lane == 0) {
        out[2 * SEQT * OUTD + hu] = hlast;
        out[2 * SEQT * OUTD + HID + hu] = c;
    }
}

// ---------------- policy head ----------------
__global__ void __launch_bounds__(128) head_kernel(
    const float* __restrict__ h2, const float* __restrict__ mean_w,
    const float* __restrict__ mean_b, const float* __restrict__ log_std,
    float* __restrict__ out)
{
    __shared__ float sh[HID];
    int t = blockIdx.x;
    for (int i = threadIdx.x; i < HID; i += 128) sh[i] = h2[(size_t)t * HID + i];
    __syncthreads();
    int w = threadIdx.x >> 5, lane = threadIdx.x & 31;
    const float* wr = mean_w + (size_t)w * HID;
    float acc = 0.f;
    for (int k = lane; k < HID; k += 32) acc = fmaf(wr[k], sh[k], acc);
    #pragma unroll
    for (int o = 16; o; o >>= 1) acc += __shfl_down_sync(0xffffffffu, acc, o);
    if (lane == 0) {
        out[(size_t)t * OUTD + w] = acc + mean_b[w];
        out[SEQT * OUTD + (size_t)t * OUTD + w] = log_std[w];
    }
}

// ---------------- launcher ----------------
extern "C" void kernel_launch(void* const* d_in, const int* in_sizes, int n_in,
                              void* d_out, int out_size)
{
    const float* x      = (const float*)d_in[0];
    const float* h0     = (const float*)d_in[1];
    const float* c0     = (const float*)d_in[2];
    const float* w_ih   = (const float*)d_in[3];
    const float* w_hh   = (const float*)d_in[4];
    const float* b_ih   = (const float*)d_in[5];
    const float* b_hh   = (const float*)d_in[6];
    const float* fc1_w  = (const float*)d_in[7];
    const float* fc1_b  = (const float*)d_in[8];
    const float* fc2_w  = (const float*)d_in[9];
    const float* fc2_b  = (const float*)d_in[10];
    const float* mean_w = (const float*)d_in[11];
    const float* mean_b = (const float*)d_in[12];
    const float* lstd   = (const float*)d_in[13];
    float* out = (float*)d_out;

    float *gx, *ys, *h1, *h2;
    cudaGetSymbolAddress((void**)&gx, g_gx);
    cudaGetSymbolAddress((void**)&ys, g_ys);
    cudaGetSymbolAddress((void**)&h1, g_h1);
    cudaGetSymbolAddress((void**)&h2, g_h2);

    // gx = x @ w_ih^T + b_ih + b_hh : [2048, 4096]
    sgemm_bt<<<dim3(G4 / 64, SEQT / 64), 256>>>(x, w_ih, b_ih, b_hh, gx,
                                                SEQT, G4, INSZ, 0);
    // reset arrival counter (same stream: ordered, graph-capturable)
    reset_kernel<<<1, 1>>>();
    // recurrence (persistent; also writes hT, cT into out)
    lstm_kernel<<<LSTM_BLOCKS, 256>>>(gx, w_hh, h0, c0, ys, out);
    // fc1, fc2 with ReLU
    sgemm_bt<<<dim3(HID / 64, SEQT / 64), 256>>>(ys, fc1_w, fc1_b, nullptr, h1,
                                                 SEQT, HID, HID, 1);
    sgemm_bt<<<dim3(HID / 64, SEQT / 64), 256>>>(h1, fc2_w, fc2_b, nullptr, h2,
                                                 SEQT, HID, HID, 1);
    // head: action_mean + action_log_std
    head_kernel<<<SEQT, 128>>>(h2, mean_w, mean_b, lstd, out);
}